// round 12
// baseline (speedup 1.0000x reference)
#include <cuda_runtime.h>
#include <cuda_bf16.h>
#include <cstdint>

#define B_ 8
#define I_ 16
#define HH 32
#define WW 32
#define CC 64
#define FF 128

// Pre-converted / transposed weights: [(b*9+kp)][f][c], bf16 hi + lo halves.
__device__ __align__(128) __nv_bfloat16 g_khi[72 * FF * CC];
__device__ __align__(128) __nv_bfloat16 g_klo[72 * FF * CC];

// ---- smem layout ------------------------------------------------------------
// Halo: 340 rows (10 ih x 34 iw) x 128B (64 bf16), hi + lo.
// B: two 32KB stages, each [128 f][64 c] hi + lo.
#define HALO_HI 0
#define HALO_LO 43520
#define BB0     87040
#define BB1     119808
#define BSTAGE_LO 16384
#define SMEM_TOTAL 152576

__device__ __forceinline__ uint32_t s2u(const void* p) {
    uint32_t a;
    asm("{ .reg .u64 t; cvta.to.shared.u64 t, %1; cvt.u32.u64 %0, t; }" : "=r"(a) : "l"(p));
    return a;
}
// pack bf16(hi_src)<<16 | bf16(lo_src)
__device__ __forceinline__ uint32_t bf2(float hi_src, float lo_src) {
    uint32_t r;
    asm("cvt.rn.bf16x2.f32 %0, %1, %2;" : "=r"(r) : "f"(hi_src), "f"(lo_src));
    return r;
}
__device__ __forceinline__ void ldsm4(uint32_t* r, uint32_t addr) {
    asm volatile("ldmatrix.sync.aligned.m8n8.x4.shared.b16 {%0,%1,%2,%3}, [%4];"
                 : "=r"(r[0]), "=r"(r[1]), "=r"(r[2]), "=r"(r[3]) : "r"(addr));
}
__device__ __forceinline__ void mma_bf16(float* d, const uint32_t* a, uint32_t b0, uint32_t b1) {
    asm volatile(
        "mma.sync.aligned.m16n8k16.row.col.f32.bf16.bf16.f32 "
        "{%0,%1,%2,%3}, {%4,%5,%6,%7}, {%8,%9}, {%0,%1,%2,%3};"
        : "+f"(d[0]), "+f"(d[1]), "+f"(d[2]), "+f"(d[3])
        : "r"(a[0]), "r"(a[1]), "r"(a[2]), "r"(a[3]), "r"(b0), "r"(b1));
}
__device__ __forceinline__ void cp16(uint32_t dst, const void* src) {
    asm volatile("cp.async.cg.shared.global [%0], [%1], 16;" :: "r"(dst), "l"(src) : "memory");
}

// ------------------------------------------------ weight convert/transpose --
// kern[b][kh][kw][c][f] f32  ->  g_khi/g_klo[(b*9+kp)][f][c] bf16
__global__ void __launch_bounds__(256) wt_convert_kernel(const float* __restrict__ kern) {
    __shared__ unsigned short shi[FF * 66];   // pad 64->66 to kill bank conflicts
    __shared__ unsigned short slo[FF * 66];
    const int blk = blockIdx.x;               // b*9+kp, 72 blocks
    const float* in = kern + (size_t)blk * (CC * FF);

    for (int idx = threadIdx.x; idx < CC * FF; idx += 256) {
        int c = idx >> 7, f = idx & 127;      // in is [c][f], reads coalesced
        float v = in[idx];
        __nv_bfloat16 h = __float2bfloat16(v);
        float hf = __bfloat162float(h);
        __nv_bfloat16 l = __float2bfloat16(v - hf);
        shi[f * 66 + c] = __bfloat16_as_ushort(h);
        slo[f * 66 + c] = __bfloat16_as_ushort(l);
    }
    __syncthreads();
    unsigned short* oh = (unsigned short*)(g_khi + (size_t)blk * (FF * CC));
    unsigned short* ol = (unsigned short*)(g_klo + (size_t)blk * (FF * CC));
    for (int idx = threadIdx.x; idx < FF * CC; idx += 256) {
        int f = idx >> 6, c = idx & 63;
        oh[idx] = shi[f * 66 + c];
        ol[idx] = slo[f * 66 + c];
    }
}

// ---------------------------------------------------------- main MMA kernel -
// Tile: M=256 (8 oh rows x 32 ow) x N=128 filters, K = 9 kp x 64 c.
// 512 threads / 16 warps: warp_m = wid&3 (4 x 64 M), warp_n = wid>>2 (4 x 32 N).
// x halo converted to bf16 hi/lo ONCE; A tiles addressed directly in the halo.
// B double-buffered via cp.async (2 stages), loads fly under compute.
// 3-term split: hi*hi + lo*hi + hi*lo.
__global__ void __launch_bounds__(512, 1)
conv_mma_kernel(const float* __restrict__ x, float* __restrict__ out)
{
    extern __shared__ char smem[];
    const uint32_t sb = s2u(smem);
    const int tid  = threadIdx.x;
    const int lane = tid & 31;
    const int wid  = tid >> 5;
    const int warp_m = wid & 3;
    const int warp_n = wid >> 2;

    const int oh0 = blockIdx.x * 8;           // 4 row-groups of 8 oh rows
    const int img = blockIdx.y;
    const int b   = blockIdx.z;
    const float* xb = x + (size_t)(b * I_ + img) * (HH * WW * CC);
    const char* kh_base = (const char*)(g_khi + (size_t)(b * 9) * (FF * CC));
    const char* kl_base = (const char*)(g_klo + (size_t)(b * 9) * (FF * CC));

    // ---- Kick off B loads for kp=0 into stage 0 (cp.async) -----------------
    {
        const char* kh_ = kh_base;
        const char* kl_ = kl_base;
        #pragma unroll
        for (int it = 0; it < 4; ++it) {
            int idx = tid + it * 512;          // 0..2047 uint4s (hi then lo)
            int t   = idx >> 10;
            int rem = idx & 1023;
            int f   = rem >> 3, u = rem & 7;
            const char* src = (t ? kl_ : kh_) + f * 128 + u * 16;
            uint32_t dst = sb + BB0 + (t ? BSTAGE_LO : 0) + f * 128 + ((u * 16) ^ ((f & 7) << 4));
            cp16(dst, src);
        }
        asm volatile("cp.async.commit_group;" ::: "memory");
    }

    // ---- Convert x halo once: rows r = ih_rel*34 + iw_rel, 340 rows --------
    for (int idx = tid; idx < 340 * 16; idx += 512) {
        int r  = idx >> 4;            // halo row
        int c4 = idx & 15;            // float4 index within 64 c
        int ih = oh0 - 1 + r / 34;
        int iw = r % 34 - 1;
        float4 v = make_float4(0.f, 0.f, 0.f, 0.f);
        if ((unsigned)ih < HH && (unsigned)iw < WW)
            v = *(const float4*)(xb + (ih * WW + iw) * CC + c4 * 4);
        uint32_t h01 = bf2(v.y, v.x);
        uint32_t h23 = bf2(v.w, v.z);
        float r0 = v.x - __uint_as_float(h01 << 16);
        float r1 = v.y - __uint_as_float(h01 & 0xFFFF0000u);
        float r2 = v.z - __uint_as_float(h23 << 16);
        float r3 = v.w - __uint_as_float(h23 & 0xFFFF0000u);
        uint32_t l01 = bf2(r1, r0);
        uint32_t l23 = bf2(r3, r2);
        uint32_t off = r * 128 + ((c4 * 8) ^ ((r & 7) << 4));   // swizzled
        *(uint2*)(smem + HALO_HI + off) = make_uint2(h01, h23);
        *(uint2*)(smem + HALO_LO + off) = make_uint2(l01, l23);
    }

    float acc[4][4][4];   // [mi][ni][reg]
    #pragma unroll
    for (int mi = 0; mi < 4; mi++)
        #pragma unroll
        for (int ni = 0; ni < 4; ni++)
            #pragma unroll
            for (int r = 0; r < 4; r++) acc[mi][ni][r] = 0.f;

    // per-lane ldmatrix address components
    const int a_m = lane & 15;                 // row within m16
    const int a_k = (lane >> 4) << 4;          // 0 / 16 byte (k half)
    const int b_n = (lane & 7) + ((lane >> 4) << 3);  // row within n16
    const int b_k = ((lane >> 3) & 1) << 4;    // 0 / 16 byte (k half)

    // halo row (minus rbase) for each mi
    int hrow[4];
    #pragma unroll
    for (int mi = 0; mi < 4; mi++) {
        int m = warp_m * 64 + mi * 16 + a_m;   // 0..255
        hrow[mi] = (m >> 5) * 34 + (m & 31);
    }
    // B ldsm row base + swizzle mask (XOR applied to FULL k-offset per ks)
    uint32_t brow[2], bmask[2];
    #pragma unroll
    for (int nj = 0; nj < 2; nj++) {
        int row = warp_n * 32 + nj * 16 + b_n;
        brow[nj]  = (uint32_t)row * 128;
        bmask[nj] = (uint32_t)((row & 7) << 4);
    }

    __syncthreads();   // halo ready

    #pragma unroll 1
    for (int kp = 0; kp < 9; ++kp) {
        const int rbase = (kp / 3) * 34 + (kp % 3);
        const uint32_t Bcur = (kp & 1) ? BB1 : BB0;

        // -- issue B loads for kp+1 into the other stage --------------------
        if (kp < 8) {
            const uint32_t Bnxt = (kp & 1) ? BB0 : BB1;
            const char* kh_ = kh_base + (size_t)(kp + 1) * (FF * CC * 2);
            const char* kl_ = kl_base + (size_t)(kp + 1) * (FF * CC * 2);
            #pragma unroll
            for (int it = 0; it < 4; ++it) {
                int idx = tid + it * 512;
                int t   = idx >> 10;
                int rem = idx & 1023;
                int f   = rem >> 3, u = rem & 7;
                const char* src = (t ? kl_ : kh_) + f * 128 + u * 16;
                uint32_t dst = sb + Bnxt + (t ? BSTAGE_LO : 0) + f * 128 + ((u * 16) ^ ((f & 7) << 4));
                cp16(dst, src);
            }
            asm volatile("cp.async.commit_group;" ::: "memory");
            asm volatile("cp.async.wait_group 1;" ::: "memory");   // kp's data done
        } else {
            asm volatile("cp.async.wait_group 0;" ::: "memory");
        }
        __syncthreads();   // B(kp) visible to all warps

        // -- compute: 4 k16-steps; A direct from halo ------------------------
        #pragma unroll
        for (int ks = 0; ks < 4; ++ks) {
            uint32_t ah[4][4], al[4][4];
            #pragma unroll
            for (int mi = 0; mi < 4; mi++) {
                int r = rbase + hrow[mi];
                uint32_t ro = (uint32_t)r * 128 + ((ks * 32 + a_k) ^ ((r & 7) << 4));
                ldsm4(ah[mi], sb + HALO_HI + ro);
                ldsm4(al[mi], sb + HALO_LO + ro);
            }
            uint32_t bh[2][4];
            #pragma unroll
            for (int nj = 0; nj < 2; nj++)
                ldsm4(bh[nj], sb + Bcur + brow[nj] + ((ks * 32 + b_k) ^ bmask[nj]));
            #pragma unroll
            for (int mi = 0; mi < 4; mi++)
                #pragma unroll
                for (int ni = 0; ni < 4; ni++)
                    mma_bf16(acc[mi][ni], ah[mi],
                             bh[ni >> 1][(ni & 1) * 2], bh[ni >> 1][(ni & 1) * 2 + 1]);
            #pragma unroll
            for (int mi = 0; mi < 4; mi++)
                #pragma unroll
                for (int ni = 0; ni < 4; ni++)
                    mma_bf16(acc[mi][ni], al[mi],
                             bh[ni >> 1][(ni & 1) * 2], bh[ni >> 1][(ni & 1) * 2 + 1]);
            uint32_t bl[2][4];
            #pragma unroll
            for (int nj = 0; nj < 2; nj++)
                ldsm4(bl[nj], sb + Bcur + BSTAGE_LO + brow[nj] + ((ks * 32 + b_k) ^ bmask[nj]));
            #pragma unroll
            for (int mi = 0; mi < 4; mi++)
                #pragma unroll
                for (int ni = 0; ni < 4; ni++)
                    mma_bf16(acc[mi][ni], ah[mi],
                             bl[ni >> 1][(ni & 1) * 2], bl[ni >> 1][(ni & 1) * 2 + 1]);
        }
        __syncthreads();   // all warps done with B(kp) before it is overwritten
    }

    // ---- epilogue: direct f32 stores (float2 per ni frag) ------------------
    const size_t obase = (size_t)(b * I_ + img) * (HH * WW);
    #pragma unroll
    for (int mi = 0; mi < 4; mi++) {
        #pragma unroll
        for (int half = 0; half < 2; half++) {
            int m  = warp_m * 64 + mi * 16 + (lane >> 2) + half * 8;
            int oh = oh0 + (m >> 5);
            int ow = m & 31;
            float* op = out + (obase + oh * WW + ow) * FF + warp_n * 32 + (lane & 3) * 2;
            #pragma unroll
            for (int ni = 0; ni < 4; ni++) {
                float2 v = make_float2(acc[mi][ni][half * 2], acc[mi][ni][half * 2 + 1]);
                *(float2*)(op + ni * 8) = v;
            }
        }
    }
}

// ----------------------------------------------------------------- launch ---
extern "C" void kernel_launch(void* const* d_in, const int* in_sizes, int n_in,
                              void* d_out, int out_size)
{
    const float* x = (const float*)d_in[0];   // (8,16,32,32,64) f32
    const float* k = (const float*)d_in[1];   // (8,3,3,64,128)  f32
    float* out = (float*)d_out;               // (8,16,32,32,128) f32

    cudaFuncSetAttribute(conv_mma_kernel,
                         cudaFuncAttributeMaxDynamicSharedMemorySize, SMEM_TOTAL);

    wt_convert_kernel<<<72, 256>>>(k);
    dim3 grid(4, 16, 8);                      // (row-group of 8, image, batch)
    conv_mma_kernel<<<grid, 512, SMEM_TOTAL>>>(x, out);
}

// round 14
// speedup vs baseline: 1.2186x; 1.2186x over previous
#include <cuda_runtime.h>
#include <cuda_bf16.h>
#include <cstdint>

#define B_ 8
#define I_ 16
#define HH 32
#define WW 32
#define CC 64
#define FF 128

// Pre-converted / transposed weights: [(b*9+kp)][f][c], bf16 hi + lo halves.
__device__ __align__(128) __nv_bfloat16 g_khi[72 * FF * CC];
__device__ __align__(128) __nv_bfloat16 g_klo[72 * FF * CC];

// ---- smem layout (same 85KB budget as R11 -> 2 CTAs/SM) --------------------
// Halo: 204 rows (6 ih x 34 iw) x 128B (64 bf16), hi + lo.
// B: one 16KB hi buffer + one 16KB lo buffer, ping-ponged in time.
#define HALO_HI 0
#define HALO_LO 26112
#define BHI     52224
#define BLO     68608
#define SMEM_TOTAL 84992

__device__ __forceinline__ uint32_t s2u(const void* p) {
    uint32_t a;
    asm("{ .reg .u64 t; cvta.to.shared.u64 t, %1; cvt.u32.u64 %0, t; }" : "=r"(a) : "l"(p));
    return a;
}
// pack bf16(hi_src)<<16 | bf16(lo_src)
__device__ __forceinline__ uint32_t bf2(float hi_src, float lo_src) {
    uint32_t r;
    asm("cvt.rn.bf16x2.f32 %0, %1, %2;" : "=r"(r) : "f"(hi_src), "f"(lo_src));
    return r;
}
__device__ __forceinline__ void ldsm4(uint32_t* r, uint32_t addr) {
    asm volatile("ldmatrix.sync.aligned.m8n8.x4.shared.b16 {%0,%1,%2,%3}, [%4];"
                 : "=r"(r[0]), "=r"(r[1]), "=r"(r[2]), "=r"(r[3]) : "r"(addr));
}
__device__ __forceinline__ void mma_bf16(float* d, const uint32_t* a, uint32_t b0, uint32_t b1) {
    asm volatile(
        "mma.sync.aligned.m16n8k16.row.col.f32.bf16.bf16.f32 "
        "{%0,%1,%2,%3}, {%4,%5,%6,%7}, {%8,%9}, {%0,%1,%2,%3};"
        : "+f"(d[0]), "+f"(d[1]), "+f"(d[2]), "+f"(d[3])
        : "r"(a[0]), "r"(a[1]), "r"(a[2]), "r"(a[3]), "r"(b0), "r"(b1));
}
__device__ __forceinline__ void cp16(uint32_t dst, const void* src) {
    asm volatile("cp.async.cg.shared.global [%0], [%1], 16;" :: "r"(dst), "l"(src) : "memory");
}
// Issue one 16KB B tile ([128 f][64 c] bf16, swizzled) into smem buf.
__device__ __forceinline__ void issue_b(uint32_t sbuf, const char* g, int tid) {
    #pragma unroll
    for (int it = 0; it < 4; ++it) {
        int idx = tid + it * 256;              // 0..1023 uint4s
        int f = idx >> 3, u = idx & 7;
        cp16(sbuf + f * 128 + ((u * 16) ^ ((f & 7) << 4)), g + f * 128 + u * 16);
    }
    asm volatile("cp.async.commit_group;" ::: "memory");
}

// ------------------------------------------------ weight convert/transpose --
// kern[b][kh][kw][c][f] f32  ->  g_khi/g_klo[(b*9+kp)][f][c] bf16
__global__ void __launch_bounds__(256) wt_convert_kernel(const float* __restrict__ kern) {
    __shared__ unsigned short shi[FF * 66];   // pad 64->66 to kill bank conflicts
    __shared__ unsigned short slo[FF * 66];
    const int blk = blockIdx.x;               // b*9+kp, 72 blocks
    const float* in = kern + (size_t)blk * (CC * FF);

    for (int idx = threadIdx.x; idx < CC * FF; idx += 256) {
        int c = idx >> 7, f = idx & 127;      // in is [c][f], reads coalesced
        float v = in[idx];
        __nv_bfloat16 h = __float2bfloat16(v);
        float hf = __bfloat162float(h);
        __nv_bfloat16 l = __float2bfloat16(v - hf);
        shi[f * 66 + c] = __bfloat16_as_ushort(h);
        slo[f * 66 + c] = __bfloat16_as_ushort(l);
    }
    __syncthreads();
    unsigned short* oh = (unsigned short*)(g_khi + (size_t)blk * (FF * CC));
    unsigned short* ol = (unsigned short*)(g_klo + (size_t)blk * (FF * CC));
    for (int idx = threadIdx.x; idx < FF * CC; idx += 256) {
        int f = idx >> 6, c = idx & 63;
        oh[idx] = shi[f * 66 + c];
        ol[idx] = slo[f * 66 + c];
    }
}

// ---------------------------------------------------------- main MMA kernel -
// Tile: M=128 (4 oh rows x 32 ow) x N=128 filters, K = 9 kp x 64 c.
// A from once-converted halo; B hi/lo half-tiles pipelined via cp.async:
//   B_lo[kp]   loads under passes 1-2 (which use B_hi[kp])
//   B_hi[kp+1] loads under pass 3     (which uses B_lo[kp])
// 3-term split: hi*hi + lo*hi + hi*lo. 8 warps: warp_m=wid&1, warp_n=wid>>1.
__global__ void __launch_bounds__(256, 2)
conv_mma_kernel(const float* __restrict__ x, float* __restrict__ out)
{
    extern __shared__ char smem[];
    const uint32_t sb = s2u(smem);
    const int tid  = threadIdx.x;
    const int lane = tid & 31;
    const int wid  = tid >> 5;
    const int warp_m = wid & 1;
    const int warp_n = wid >> 1;

    const int oh0 = blockIdx.x * 4;
    const int img = blockIdx.y;
    const int b   = blockIdx.z;
    const float* xb = x + (size_t)(b * I_ + img) * (HH * WW * CC);
    const char* kh_base = (const char*)(g_khi + (size_t)(b * 9) * (FF * CC));
    const char* kl_base = (const char*)(g_klo + (size_t)(b * 9) * (FF * CC));

    // Prologue: start B_hi[0] immediately; it lands during halo convert.
    issue_b(sb + BHI, kh_base, tid);

    // ---- Convert x halo once: rows r = ih_rel*34 + iw_rel, 204 rows --------
    for (int idx = tid; idx < 204 * 16; idx += 256) {
        int r  = idx >> 4;            // halo row
        int c4 = idx & 15;            // float4 index within 64 c
        int ih = oh0 - 1 + r / 34;
        int iw = r % 34 - 1;
        float4 v = make_float4(0.f, 0.f, 0.f, 0.f);
        if ((unsigned)ih < HH && (unsigned)iw < WW)
            v = *(const float4*)(xb + (ih * WW + iw) * CC + c4 * 4);
        uint32_t h01 = bf2(v.y, v.x);
        uint32_t h23 = bf2(v.w, v.z);
        float r0 = v.x - __uint_as_float(h01 << 16);
        float r1 = v.y - __uint_as_float(h01 & 0xFFFF0000u);
        float r2 = v.z - __uint_as_float(h23 << 16);
        float r3 = v.w - __uint_as_float(h23 & 0xFFFF0000u);
        uint32_t l01 = bf2(r1, r0);
        uint32_t l23 = bf2(r3, r2);
        uint32_t off = r * 128 + ((c4 * 8) ^ ((r & 7) << 4));   // swizzled
        *(uint2*)(smem + HALO_HI + off) = make_uint2(h01, h23);
        *(uint2*)(smem + HALO_LO + off) = make_uint2(l01, l23);
    }

    float acc[4][4][4];   // [mi][ni][reg]
    #pragma unroll
    for (int mi = 0; mi < 4; mi++)
        #pragma unroll
        for (int ni = 0; ni < 4; ni++)
            #pragma unroll
            for (int r = 0; r < 4; r++) acc[mi][ni][r] = 0.f;

    // per-lane ldmatrix address components
    const int a_m = lane & 15;                 // row within m16
    const int a_k = (lane >> 4) << 4;          // 0 / 16 byte (k half)
    const int b_n = (lane & 7) + ((lane >> 4) << 3);  // row within n16
    const int b_k = ((lane >> 3) & 1) << 4;    // 0 / 16 byte (k half)

    // halo row (minus rbase) for each mi
    int hrow[4];
    #pragma unroll
    for (int mi = 0; mi < 4; mi++) {
        int m = warp_m * 64 + mi * 16 + a_m;
        hrow[mi] = (m >> 5) * 34 + (m & 31);
    }
    // B ldsm row base + swizzle mask (XOR applied to FULL k-offset per ks)
    uint32_t brow[2], bmask[2];
    #pragma unroll
    for (int nj = 0; nj < 2; nj++) {
        int row = warp_n * 32 + nj * 16 + b_n;
        brow[nj]  = (uint32_t)row * 128;
        bmask[nj] = (uint32_t)((row & 7) << 4);
    }

    #pragma unroll 1
    for (int kp = 0; kp < 9; ++kp) {
        const int rbase = (kp / 3) * 34 + (kp % 3);

        // B_hi[kp] is the only (or oldest) outstanding group -> wait it out.
        asm volatile("cp.async.wait_group 0;" ::: "memory");
        __syncthreads();   // B_hi[kp] visible; prev pass3 / halo writes done

        // B_lo[kp] loads while passes 1-2 run on B_hi[kp]
        issue_b(sb + BLO, kl_base + (size_t)kp * (FF * CC * 2), tid);

        // -- passes 1-2: hi*hi and lo*hi (both consume B_hi) -----------------
        #pragma unroll
        for (int ks = 0; ks < 4; ++ks) {
            uint32_t ah[4][4], al[4][4];
            #pragma unroll
            for (int mi = 0; mi < 4; mi++) {
                int r = rbase + hrow[mi];
                uint32_t ro = (uint32_t)r * 128 + ((ks * 32 + a_k) ^ ((r & 7) << 4));
                ldsm4(ah[mi], sb + HALO_HI + ro);
                ldsm4(al[mi], sb + HALO_LO + ro);
            }
            uint32_t bh[2][4];
            #pragma unroll
            for (int nj = 0; nj < 2; nj++)
                ldsm4(bh[nj], sb + BHI + brow[nj] + ((ks * 32 + b_k) ^ bmask[nj]));
            #pragma unroll
            for (int mi = 0; mi < 4; mi++)
                #pragma unroll
                for (int ni = 0; ni < 4; ni++)
                    mma_bf16(acc[mi][ni], ah[mi],
                             bh[ni >> 1][(ni & 1) * 2], bh[ni >> 1][(ni & 1) * 2 + 1]);
            #pragma unroll
            for (int mi = 0; mi < 4; mi++)
                #pragma unroll
                for (int ni = 0; ni < 4; ni++)
                    mma_bf16(acc[mi][ni], al[mi],
                             bh[ni >> 1][(ni & 1) * 2], bh[ni >> 1][(ni & 1) * 2 + 1]);
        }
        __syncthreads();   // all warps done with B_hi buffer

        if (kp < 8) {
            // B_hi[kp+1] loads while pass 3 runs on B_lo[kp]
            issue_b(sb + BHI, kh_base + (size_t)(kp + 1) * (FF * CC * 2), tid);
            asm volatile("cp.async.wait_group 1;" ::: "memory");  // B_lo[kp] done
        } else {
            asm volatile("cp.async.wait_group 0;" ::: "memory");
        }
        __syncthreads();   // B_lo[kp] visible

        // -- pass 3: hi*lo (consumes B_lo) -----------------------------------
        #pragma unroll
        for (int ks = 0; ks < 4; ++ks) {
            uint32_t ah[4][4];
            #pragma unroll
            for (int mi = 0; mi < 4; mi++) {
                int r = rbase + hrow[mi];
                uint32_t ro = (uint32_t)r * 128 + ((ks * 32 + a_k) ^ ((r & 7) << 4));
                ldsm4(ah[mi], sb + HALO_HI + ro);
            }
            uint32_t bl[2][4];
            #pragma unroll
            for (int nj = 0; nj < 2; nj++)
                ldsm4(bl[nj], sb + BLO + brow[nj] + ((ks * 32 + b_k) ^ bmask[nj]));
            #pragma unroll
            for (int mi = 0; mi < 4; mi++)
                #pragma unroll
                for (int ni = 0; ni < 4; ni++)
                    mma_bf16(acc[mi][ni], ah[mi],
                             bl[ni >> 1][(ni & 1) * 2], bl[ni >> 1][(ni & 1) * 2 + 1]);
        }
        // Next iteration's top sync protects B_lo before it is overwritten.
    }

    // ---- epilogue: direct f32 stores (float2 per ni frag) ------------------
    const size_t obase = (size_t)(b * I_ + img) * (HH * WW);
    #pragma unroll
    for (int mi = 0; mi < 4; mi++) {
        #pragma unroll
        for (int half = 0; half < 2; half++) {
            int m  = warp_m * 64 + mi * 16 + (lane >> 2) + half * 8;
            int oh = oh0 + (m >> 5);
            int ow = m & 31;
            float* op = out + (obase + oh * WW + ow) * FF + warp_n * 32 + (lane & 3) * 2;
            #pragma unroll
            for (int ni = 0; ni < 4; ni++) {
                float2 v = make_float2(acc[mi][ni][half * 2], acc[mi][ni][half * 2 + 1]);
                *(float2*)(op + ni * 8) = v;
            }
        }
    }
}

// ----------------------------------------------------------------- launch ---
extern "C" void kernel_launch(void* const* d_in, const int* in_sizes, int n_in,
                              void* d_out, int out_size)
{
    const float* x = (const float*)d_in[0];   // (8,16,32,32,64) f32
    const float* k = (const float*)d_in[1];   // (8,3,3,64,128)  f32
    float* out = (float*)d_out;               // (8,16,32,32,128) f32

    cudaFuncSetAttribute(conv_mma_kernel,
                         cudaFuncAttributeMaxDynamicSharedMemorySize, SMEM_TOTAL);

    wt_convert_kernel<<<72, 256>>>(k);
    dim3 grid(8, 16, 8);                      // (row-group, image, batch)
    conv_mma_kernel<<<grid, 256, SMEM_TOTAL>>>(x, out);
}

// round 15
// speedup vs baseline: 1.2703x; 1.0424x over previous
#include <cuda_runtime.h>
#include <cuda_bf16.h>
#include <cstdint>

#define B_ 8
#define I_ 16
#define HH 32
#define WW 32
#define CC 64
#define FF 128

// Pre-converted / transposed weights: [(b*9+kp)][f][c], bf16 hi + lo halves.
__device__ __align__(128) __nv_bfloat16 g_khi[72 * FF * CC];
__device__ __align__(128) __nv_bfloat16 g_klo[72 * FF * CC];

// ---- smem layout (111,616 B/CTA -> 2 CTAs/SM) ------------------------------
// Tile: 8 oh x 16 ow. Halo: 180 rows (10 ih x 18 iw) x 128B, hi + lo.
// B: TWO full 32KB stages (hi at +0, lo at +16384 within each).
#define HALO_HI 0
#define HALO_LO 23040
#define BB0     46080
#define BB1     78848
#define BSTAGE_LO 16384
#define SMEM_TOTAL 111616

__device__ __forceinline__ uint32_t s2u(const void* p) {
    uint32_t a;
    asm("{ .reg .u64 t; cvta.to.shared.u64 t, %1; cvt.u32.u64 %0, t; }" : "=r"(a) : "l"(p));
    return a;
}
// pack bf16(hi_src)<<16 | bf16(lo_src)
__device__ __forceinline__ uint32_t bf2(float hi_src, float lo_src) {
    uint32_t r;
    asm("cvt.rn.bf16x2.f32 %0, %1, %2;" : "=r"(r) : "f"(hi_src), "f"(lo_src));
    return r;
}
__device__ __forceinline__ void ldsm4(uint32_t* r, uint32_t addr) {
    asm volatile("ldmatrix.sync.aligned.m8n8.x4.shared.b16 {%0,%1,%2,%3}, [%4];"
                 : "=r"(r[0]), "=r"(r[1]), "=r"(r[2]), "=r"(r[3]) : "r"(addr));
}
__device__ __forceinline__ void mma_bf16(float* d, const uint32_t* a, uint32_t b0, uint32_t b1) {
    asm volatile(
        "mma.sync.aligned.m16n8k16.row.col.f32.bf16.bf16.f32 "
        "{%0,%1,%2,%3}, {%4,%5,%6,%7}, {%8,%9}, {%0,%1,%2,%3};"
        : "+f"(d[0]), "+f"(d[1]), "+f"(d[2]), "+f"(d[3])
        : "r"(a[0]), "r"(a[1]), "r"(a[2]), "r"(a[3]), "r"(b0), "r"(b1));
}
__device__ __forceinline__ void cp16(uint32_t dst, const void* src) {
    asm volatile("cp.async.cg.shared.global [%0], [%1], 16;" :: "r"(dst), "l"(src) : "memory");
}
// Issue one FULL 32KB B stage (hi tile then lo tile, swizzled), one group.
__device__ __forceinline__ void issue_b_stage(uint32_t sstage, const char* ghi,
                                              const char* glo, int tid) {
    #pragma unroll
    for (int it = 0; it < 8; ++it) {
        int idx = tid + it * 256;              // 0..2047 uint4s (hi then lo)
        int t   = idx >> 10;
        int rem = idx & 1023;
        int f   = rem >> 3, u = rem & 7;
        const char* src = (t ? glo : ghi) + f * 128 + u * 16;
        cp16(sstage + (t ? BSTAGE_LO : 0) + f * 128 + ((u * 16) ^ ((f & 7) << 4)), src);
    }
    asm volatile("cp.async.commit_group;" ::: "memory");
}

// ------------------------------------------------ weight convert/transpose --
// kern[b][kh][kw][c][f] f32  ->  g_khi/g_klo[(b*9+kp)][f][c] bf16
__global__ void __launch_bounds__(256) wt_convert_kernel(const float* __restrict__ kern) {
    __shared__ unsigned short shi[FF * 66];   // pad 64->66 to kill bank conflicts
    __shared__ unsigned short slo[FF * 66];
    const int blk = blockIdx.x;               // b*9+kp, 72 blocks
    const float* in = kern + (size_t)blk * (CC * FF);

    for (int idx = threadIdx.x; idx < CC * FF; idx += 256) {
        int c = idx >> 7, f = idx & 127;      // in is [c][f], reads coalesced
        float v = in[idx];
        __nv_bfloat16 h = __float2bfloat16(v);
        float hf = __bfloat162float(h);
        __nv_bfloat16 l = __float2bfloat16(v - hf);
        shi[f * 66 + c] = __bfloat16_as_ushort(h);
        slo[f * 66 + c] = __bfloat16_as_ushort(l);
    }
    __syncthreads();
    unsigned short* oh = (unsigned short*)(g_khi + (size_t)blk * (FF * CC));
    unsigned short* ol = (unsigned short*)(g_klo + (size_t)blk * (FF * CC));
    for (int idx = threadIdx.x; idx < FF * CC; idx += 256) {
        int f = idx >> 6, c = idx & 63;
        oh[idx] = shi[f * 66 + c];
        ol[idx] = slo[f * 66 + c];
    }
}

// ---------------------------------------------------------- main MMA kernel -
// Tile: M=128 (8 oh x 16 ow) x N=128 filters, K = 9 kp x 64 c.
// A from once-converted halo; B FULLY double-buffered (2x32KB stages, one
// cp.async group per kp) -> single merged compute loop, 48 MMAs per ks.
// 3-term split: hi*hi + lo*hi + hi*lo. 8 warps: warp_m=wid&1, warp_n=wid>>1.
__global__ void __launch_bounds__(256, 2)
conv_mma_kernel(const float* __restrict__ x, float* __restrict__ out)
{
    extern __shared__ char smem[];
    const uint32_t sb = s2u(smem);
    const int tid  = threadIdx.x;
    const int lane = tid & 31;
    const int wid  = tid >> 5;
    const int warp_m = wid & 1;
    const int warp_n = wid >> 1;

    const int oh0 = (blockIdx.x >> 1) * 8;    // 4 oh-groups of 8 rows
    const int ow0 = (blockIdx.x & 1) * 16;    // 2 ow-groups of 16 cols
    const int img = blockIdx.y;
    const int b   = blockIdx.z;
    const float* xb = x + (size_t)(b * I_ + img) * (HH * WW * CC);
    const char* kh_base = (const char*)(g_khi + (size_t)(b * 9) * (FF * CC));
    const char* kl_base = (const char*)(g_klo + (size_t)(b * 9) * (FF * CC));

    // Prologue: start B[0] into stage 0; it lands during halo convert.
    issue_b_stage(sb + BB0, kh_base, kl_base, tid);

    // ---- Convert x halo once: rows r = ih_rel*18 + iw_rel, 180 rows --------
    for (int idx = tid; idx < 180 * 16; idx += 256) {
        int r  = idx >> 4;            // halo row
        int c4 = idx & 15;            // float4 index within 64 c
        int ih = oh0 - 1 + r / 18;
        int iw = ow0 - 1 + r % 18;
        float4 v = make_float4(0.f, 0.f, 0.f, 0.f);
        if ((unsigned)ih < HH && (unsigned)iw < WW)
            v = *(const float4*)(xb + (ih * WW + iw) * CC + c4 * 4);
        uint32_t h01 = bf2(v.y, v.x);
        uint32_t h23 = bf2(v.w, v.z);
        float r0 = v.x - __uint_as_float(h01 << 16);
        float r1 = v.y - __uint_as_float(h01 & 0xFFFF0000u);
        float r2 = v.z - __uint_as_float(h23 << 16);
        float r3 = v.w - __uint_as_float(h23 & 0xFFFF0000u);
        uint32_t l01 = bf2(r1, r0);
        uint32_t l23 = bf2(r3, r2);
        uint32_t off = r * 128 + ((c4 * 8) ^ ((r & 7) << 4));   // swizzled
        *(uint2*)(smem + HALO_HI + off) = make_uint2(h01, h23);
        *(uint2*)(smem + HALO_LO + off) = make_uint2(l01, l23);
    }

    float acc[4][4][4];   // [mi][ni][reg]
    #pragma unroll
    for (int mi = 0; mi < 4; mi++)
        #pragma unroll
        for (int ni = 0; ni < 4; ni++)
            #pragma unroll
            for (int r = 0; r < 4; r++) acc[mi][ni][r] = 0.f;

    // per-lane ldmatrix address components
    const int a_m = lane & 15;                 // row within m16
    const int a_k = (lane >> 4) << 4;          // 0 / 16 byte (k half)
    const int b_n = (lane & 7) + ((lane >> 4) << 3);  // row within n16
    const int b_k = ((lane >> 3) & 1) << 4;    // 0 / 16 byte (k half)

    // halo row (minus rbase) for each mi:  m = oh_rel*16 + ow_rel
    int hrow[4];
    #pragma unroll
    for (int mi = 0; mi < 4; mi++) {
        int m = warp_m * 64 + mi * 16 + a_m;
        hrow[mi] = (m >> 4) * 18 + (m & 15);
    }
    // B ldsm row base + swizzle mask (XOR applied to FULL k-offset per ks)
    uint32_t brow[2], bmask[2];
    #pragma unroll
    for (int nj = 0; nj < 2; nj++) {
        int row = warp_n * 32 + nj * 16 + b_n;
        brow[nj]  = (uint32_t)row * 128;
        bmask[nj] = (uint32_t)((row & 7) << 4);
    }

    __syncthreads();   // halo ready

    #pragma unroll 1
    for (int kp = 0; kp < 9; ++kp) {
        const int rbase = (kp / 3) * 18 + (kp % 3);
        const uint32_t Bcur = (kp & 1) ? BB1 : BB0;

        // Issue B[kp+1] into the other stage, then retire B[kp]'s group.
        if (kp < 8) {
            const uint32_t Bnxt = (kp & 1) ? BB0 : BB1;
            issue_b_stage(sb + Bnxt, kh_base + (size_t)(kp + 1) * (FF * CC * 2),
                          kl_base + (size_t)(kp + 1) * (FF * CC * 2), tid);
            asm volatile("cp.async.wait_group 1;" ::: "memory");   // B[kp] done
        } else {
            asm volatile("cp.async.wait_group 0;" ::: "memory");
        }
        __syncthreads();   // B[kp] visible; prev kp's consumers drained

        // -- merged compute: 4 k16-steps, all 3 passes back-to-back ----------
        #pragma unroll
        for (int ks = 0; ks < 4; ++ks) {
            uint32_t ah[4][4], al[4][4];
            #pragma unroll
            for (int mi = 0; mi < 4; mi++) {
                int r = rbase + hrow[mi];
                uint32_t ro = (uint32_t)r * 128 + ((ks * 32 + a_k) ^ ((r & 7) << 4));
                ldsm4(ah[mi], sb + HALO_HI + ro);
                ldsm4(al[mi], sb + HALO_LO + ro);
            }
            uint32_t bh[2][4], bl[2][4];
            #pragma unroll
            for (int nj = 0; nj < 2; nj++) {
                uint32_t ko = (ks * 32 + b_k);
                ldsm4(bh[nj], sb + Bcur + brow[nj] + (ko ^ bmask[nj]));
                ldsm4(bl[nj], sb + Bcur + BSTAGE_LO + brow[nj] + (ko ^ bmask[nj]));
            }
            #pragma unroll
            for (int mi = 0; mi < 4; mi++)
                #pragma unroll
                for (int ni = 0; ni < 4; ni++)
                    mma_bf16(acc[mi][ni], ah[mi],
                             bh[ni >> 1][(ni & 1) * 2], bh[ni >> 1][(ni & 1) * 2 + 1]);
            #pragma unroll
            for (int mi = 0; mi < 4; mi++)
                #pragma unroll
                for (int ni = 0; ni < 4; ni++)
                    mma_bf16(acc[mi][ni], al[mi],
                             bh[ni >> 1][(ni & 1) * 2], bh[ni >> 1][(ni & 1) * 2 + 1]);
            #pragma unroll
            for (int mi = 0; mi < 4; mi++)
                #pragma unroll
                for (int ni = 0; ni < 4; ni++)
                    mma_bf16(acc[mi][ni], ah[mi],
                             bl[ni >> 1][(ni & 1) * 2], bl[ni >> 1][(ni & 1) * 2 + 1]);
        }
        __syncthreads();   // all warps done with B[kp] before its stage refills
    }

    // ---- epilogue: direct f32 stores (float2 per ni frag) ------------------
    const size_t obase = (size_t)(b * I_ + img) * (HH * WW);
    #pragma unroll
    for (int mi = 0; mi < 4; mi++) {
        #pragma unroll
        for (int half = 0; half < 2; half++) {
            int m  = warp_m * 64 + mi * 16 + (lane >> 2) + half * 8;
            int oh = oh0 + (m >> 4);
            int ow = ow0 + (m & 15);
            float* op = out + (obase + oh * WW + ow) * FF + warp_n * 32 + (lane & 3) * 2;
            #pragma unroll
            for (int ni = 0; ni < 4; ni++) {
                float2 v = make_float2(acc[mi][ni][half * 2], acc[mi][ni][half * 2 + 1]);
                *(float2*)(op + ni * 8) = v;
            }
        }
    }
}

// ----------------------------------------------------------------- launch ---
extern "C" void kernel_launch(void* const* d_in, const int* in_sizes, int n_in,
                              void* d_out, int out_size)
{
    const float* x = (const float*)d_in[0];   // (8,16,32,32,64) f32
    const float* k = (const float*)d_in[1];   // (8,3,3,64,128)  f32
    float* out = (float*)d_out;               // (8,16,32,32,128) f32

    cudaFuncSetAttribute(conv_mma_kernel,
                         cudaFuncAttributeMaxDynamicSharedMemorySize, SMEM_TOTAL);

    wt_convert_kernel<<<72, 256>>>(k);
    dim3 grid(8, 16, 8);                      // ((oh_grp, ow_grp), image, batch)
    conv_mma_kernel<<<grid, 256, SMEM_TOTAL>>>(x, out);
}

// round 16
// speedup vs baseline: 2.4112x; 1.8982x over previous
#include <cuda_runtime.h>
#include <cuda_fp16.h>
#include <cstdint>

#define B_ 8
#define I_ 16
#define HH 32
#define WW 32
#define CC 64
#define FF 128

// Pre-converted / transposed weights: [(b*9+kp)][f][c], fp16.
__device__ __align__(128) __half g_kf16[72 * FF * CC];

// ---- smem layout (55,808 B/CTA -> 2 CTAs/SM with headroom) -----------------
// Tile: 8 oh x 16 ow. Halo: 180 rows (10 ih x 18 iw) x 128B (64 fp16).
// B: TWO 16KB stages, double-buffered.
#define HALO    0
#define BB0     23040
#define BB1     39424
#define SMEM_TOTAL 55808

__device__ __forceinline__ uint32_t s2u(const void* p) {
    uint32_t a;
    asm("{ .reg .u64 t; cvta.to.shared.u64 t, %1; cvt.u32.u64 %0, t; }" : "=r"(a) : "l"(p));
    return a;
}
__device__ __forceinline__ void ldsm4(uint32_t* r, uint32_t addr) {
    asm volatile("ldmatrix.sync.aligned.m8n8.x4.shared.b16 {%0,%1,%2,%3}, [%4];"
                 : "=r"(r[0]), "=r"(r[1]), "=r"(r[2]), "=r"(r[3]) : "r"(addr));
}
__device__ __forceinline__ void mma_f16(float* d, const uint32_t* a, uint32_t b0, uint32_t b1) {
    asm volatile(
        "mma.sync.aligned.m16n8k16.row.col.f32.f16.f16.f32 "
        "{%0,%1,%2,%3}, {%4,%5,%6,%7}, {%8,%9}, {%0,%1,%2,%3};"
        : "+f"(d[0]), "+f"(d[1]), "+f"(d[2]), "+f"(d[3])
        : "r"(a[0]), "r"(a[1]), "r"(a[2]), "r"(a[3]), "r"(b0), "r"(b1));
}
__device__ __forceinline__ void cp16(uint32_t dst, const void* src) {
    asm volatile("cp.async.cg.shared.global [%0], [%1], 16;" :: "r"(dst), "l"(src) : "memory");
}
// Issue one 16KB fp16 B tile ([128 f][64 c], swizzled) as one cp.async group.
__device__ __forceinline__ void issue_b_stage(uint32_t sstage, const char* g, int tid) {
    #pragma unroll
    for (int it = 0; it < 4; ++it) {
        int idx = tid + it * 256;              // 0..1023 uint4s
        int f = idx >> 3, u = idx & 7;
        cp16(sstage + f * 128 + ((u * 16) ^ ((f & 7) << 4)), g + f * 128 + u * 16);
    }
    asm volatile("cp.async.commit_group;" ::: "memory");
}

// ------------------------------------------------ weight convert/transpose --
// kern[b][kh][kw][c][f] f32  ->  g_kf16[(b*9+kp)][f][c] fp16
__global__ void __launch_bounds__(256) wt_convert_kernel(const float* __restrict__ kern) {
    __shared__ unsigned short sw[FF * 66];    // pad 64->66 to kill bank conflicts
    const int blk = blockIdx.x;               // b*9+kp, 72 blocks
    const float* in = kern + (size_t)blk * (CC * FF);

    for (int idx = threadIdx.x; idx < CC * FF; idx += 256) {
        int c = idx >> 7, f = idx & 127;      // in is [c][f], reads coalesced
        sw[f * 66 + c] = __half_as_ushort(__float2half_rn(in[idx]));
    }
    __syncthreads();
    unsigned short* o = (unsigned short*)(g_kf16 + (size_t)blk * (FF * CC));
    for (int idx = threadIdx.x; idx < FF * CC; idx += 256) {
        int f = idx >> 6, c = idx & 63;
        o[idx] = sw[f * 66 + c];
    }
}

// ---------------------------------------------------------- main MMA kernel -
// Tile: M=128 (8 oh x 16 ow) x N=128 filters, K = 9 kp x 64 c. Single-pass
// fp16 (e5m11): rel_err ~4e-4 < 1e-3. A from once-converted fp16 halo;
// B double-buffered via cp.async. 8 warps: warp_m=wid&1, warp_n=wid>>1.
__global__ void __launch_bounds__(256, 2)
conv_mma_kernel(const float* __restrict__ x, float* __restrict__ out)
{
    extern __shared__ char smem[];
    const uint32_t sb = s2u(smem);
    const int tid  = threadIdx.x;
    const int lane = tid & 31;
    const int wid  = tid >> 5;
    const int warp_m = wid & 1;
    const int warp_n = wid >> 1;

    const int oh0 = (blockIdx.x >> 1) * 8;    // 4 oh-groups of 8 rows
    const int ow0 = (blockIdx.x & 1) * 16;    // 2 ow-groups of 16 cols
    const int img = blockIdx.y;
    const int b   = blockIdx.z;
    const float* xb = x + (size_t)(b * I_ + img) * (HH * WW * CC);
    const char* kf_base = (const char*)(g_kf16 + (size_t)(b * 9) * (FF * CC));

    // Prologue: start B[0] into stage 0; it lands during halo convert.
    issue_b_stage(sb + BB0, kf_base, tid);

    // ---- Convert x halo once to fp16: rows r = ih_rel*18 + iw_rel ----------
    for (int idx = tid; idx < 180 * 16; idx += 256) {
        int r  = idx >> 4;            // halo row
        int c4 = idx & 15;            // float4 index within 64 c
        int ih = oh0 - 1 + r / 18;
        int iw = ow0 - 1 + r % 18;
        float4 v = make_float4(0.f, 0.f, 0.f, 0.f);
        if ((unsigned)ih < HH && (unsigned)iw < WW)
            v = *(const float4*)(xb + (ih * WW + iw) * CC + c4 * 4);
        __half2 h01 = __floats2half2_rn(v.x, v.y);
        __half2 h23 = __floats2half2_rn(v.z, v.w);
        uint32_t off = r * 128 + ((c4 * 8) ^ ((r & 7) << 4));   // swizzled
        *(uint2*)(smem + HALO + off) =
            make_uint2(*(uint32_t*)&h01, *(uint32_t*)&h23);
    }

    float acc[4][4][4];   // [mi][ni][reg]
    #pragma unroll
    for (int mi = 0; mi < 4; mi++)
        #pragma unroll
        for (int ni = 0; ni < 4; ni++)
            #pragma unroll
            for (int r = 0; r < 4; r++) acc[mi][ni][r] = 0.f;

    // per-lane ldmatrix address components
    const int a_m = lane & 15;                 // row within m16
    const int a_k = (lane >> 4) << 4;          // 0 / 16 byte (k half)
    const int b_n = (lane & 7) + ((lane >> 4) << 3);  // row within n16
    const int b_k = ((lane >> 3) & 1) << 4;    // 0 / 16 byte (k half)

    // halo row (minus rbase) for each mi:  m = oh_rel*16 + ow_rel
    int hrow[4];
    #pragma unroll
    for (int mi = 0; mi < 4; mi++) {
        int m = warp_m * 64 + mi * 16 + a_m;
        hrow[mi] = (m >> 4) * 18 + (m & 15);
    }
    // B ldsm row base + swizzle mask (XOR applied to FULL k-offset per ks)
    uint32_t brow[2], bmask[2];
    #pragma unroll
    for (int nj = 0; nj < 2; nj++) {
        int row = warp_n * 32 + nj * 16 + b_n;
        brow[nj]  = (uint32_t)row * 128;
        bmask[nj] = (uint32_t)((row & 7) << 4);
    }

    __syncthreads();   // halo ready

    #pragma unroll 1
    for (int kp = 0; kp < 9; ++kp) {
        const int rbase = (kp / 3) * 18 + (kp % 3);
        const uint32_t Bcur = (kp & 1) ? BB1 : BB0;

        // Issue B[kp+1] into the other stage, then retire B[kp]'s group.
        if (kp < 8) {
            const uint32_t Bnxt = (kp & 1) ? BB0 : BB1;
            issue_b_stage(sb + Bnxt, kf_base + (size_t)(kp + 1) * (FF * CC * 2), tid);
            asm volatile("cp.async.wait_group 1;" ::: "memory");   // B[kp] done
        } else {
            asm volatile("cp.async.wait_group 0;" ::: "memory");
        }
        __syncthreads();   // B[kp] visible; prev kp's consumers drained

        // -- compute: 4 k16-steps, 16 MMAs each ------------------------------
        #pragma unroll
        for (int ks = 0; ks < 4; ++ks) {
            uint32_t ah[4][4];
            #pragma unroll
            for (int mi = 0; mi < 4; mi++) {
                int r = rbase + hrow[mi];
                uint32_t ro = (uint32_t)r * 128 + ((ks * 32 + a_k) ^ ((r & 7) << 4));
                ldsm4(ah[mi], sb + HALO + ro);
            }
            uint32_t bh[2][4];
            #pragma unroll
            for (int nj = 0; nj < 2; nj++)
                ldsm4(bh[nj], sb + Bcur + brow[nj] + ((ks * 32 + b_k) ^ bmask[nj]));
            #pragma unroll
            for (int mi = 0; mi < 4; mi++)
                #pragma unroll
                for (int ni = 0; ni < 4; ni++)
                    mma_f16(acc[mi][ni], ah[mi],
                            bh[ni >> 1][(ni & 1) * 2], bh[ni >> 1][(ni & 1) * 2 + 1]);
        }
        __syncthreads();   // all warps done with B[kp] before its stage refills
    }

    // ---- epilogue: direct f32 stores (float2 per ni frag) ------------------
    const size_t obase = (size_t)(b * I_ + img) * (HH * WW);
    #pragma unroll
    for (int mi = 0; mi < 4; mi++) {
        #pragma unroll
        for (int half = 0; half < 2; half++) {
            int m  = warp_m * 64 + mi * 16 + (lane >> 2) + half * 8;
            int oh = oh0 + (m >> 4);
            int ow = ow0 + (m & 15);
            float* op = out + (obase + oh * WW + ow) * FF + warp_n * 32 + (lane & 3) * 2;
            #pragma unroll
            for (int ni = 0; ni < 4; ni++) {
                float2 v = make_float2(acc[mi][ni][half * 2], acc[mi][ni][half * 2 + 1]);
                *(float2*)(op + ni * 8) = v;
            }
        }
    }
}

// ----------------------------------------------------------------- launch ---
extern "C" void kernel_launch(void* const* d_in, const int* in_sizes, int n_in,
                              void* d_out, int out_size)
{
    const float* x = (const float*)d_in[0];   // (8,16,32,32,64) f32
    const float* k = (const float*)d_in[1];   // (8,3,3,64,128)  f32
    float* out = (float*)d_out;               // (8,16,32,32,128) f32

    cudaFuncSetAttribute(conv_mma_kernel,
                         cudaFuncAttributeMaxDynamicSharedMemorySize, SMEM_TOTAL);

    wt_convert_kernel<<<72, 256>>>(k);
    dim3 grid(8, 16, 8);                      // ((oh_grp, ow_grp), image, batch)
    conv_mma_kernel<<<grid, 256, SMEM_TOTAL>>>(x, out);
}

// round 17
// speedup vs baseline: 2.4505x; 1.0163x over previous
#include <cuda_runtime.h>
#include <cuda_fp16.h>
#include <cstdint>

#define B_ 8
#define I_ 16
#define HH 32
#define WW 32
#define CC 64
#define FF 128

// Pre-converted / transposed weights: [(b*9+kp)][f][c], fp16.
__device__ __align__(128) __half g_kf16[72 * FF * CC];

// ---- smem layout (72,192 B/CTA -> 2 CTAs/SM) -------------------------------
// Tile: 8 oh x 16 ow. Halo: 180 rows (10 ih x 18 iw) x 128B (64 fp16).
// B: THREE 16KB stages in a ring -> single barrier per kp.
#define HALO    0
#define BBASE   23040
#define BSTAGE  16384
#define SMEM_TOTAL 72192

__device__ __forceinline__ uint32_t s2u(const void* p) {
    uint32_t a;
    asm("{ .reg .u64 t; cvta.to.shared.u64 t, %1; cvt.u32.u64 %0, t; }" : "=r"(a) : "l"(p));
    return a;
}
__device__ __forceinline__ void ldsm4(uint32_t* r, uint32_t addr) {
    asm volatile("ldmatrix.sync.aligned.m8n8.x4.shared.b16 {%0,%1,%2,%3}, [%4];"
                 : "=r"(r[0]), "=r"(r[1]), "=r"(r[2]), "=r"(r[3]) : "r"(addr));
}
__device__ __forceinline__ void mma_f16(float* d, const uint32_t* a, uint32_t b0, uint32_t b1) {
    asm volatile(
        "mma.sync.aligned.m16n8k16.row.col.f32.f16.f16.f32 "
        "{%0,%1,%2,%3}, {%4,%5,%6,%7}, {%8,%9}, {%0,%1,%2,%3};"
        : "+f"(d[0]), "+f"(d[1]), "+f"(d[2]), "+f"(d[3])
        : "r"(a[0]), "r"(a[1]), "r"(a[2]), "r"(a[3]), "r"(b0), "r"(b1));
}
__device__ __forceinline__ void cp16(uint32_t dst, const void* src) {
    asm volatile("cp.async.cg.shared.global [%0], [%1], 16;" :: "r"(dst), "l"(src) : "memory");
}
// Issue one 16KB fp16 B tile ([128 f][64 c], swizzled) as one cp.async group.
__device__ __forceinline__ void issue_b_stage(uint32_t sstage, const char* g, int tid) {
    #pragma unroll
    for (int it = 0; it < 4; ++it) {
        int idx = tid + it * 256;              // 0..1023 uint4s
        int f = idx >> 3, u = idx & 7;
        cp16(sstage + f * 128 + ((u * 16) ^ ((f & 7) << 4)), g + f * 128 + u * 16);
    }
    asm volatile("cp.async.commit_group;" ::: "memory");
}

// ------------------------------------------------ weight convert/transpose --
// kern[b][kh][kw][c][f] f32  ->  g_kf16[(b*9+kp)][f][c] fp16
__global__ void __launch_bounds__(256) wt_convert_kernel(const float* __restrict__ kern) {
    __shared__ unsigned short sw[FF * 66];    // pad 64->66 to kill bank conflicts
    const int blk = blockIdx.x;               // b*9+kp, 72 blocks
    const float* in = kern + (size_t)blk * (CC * FF);

    for (int idx = threadIdx.x; idx < CC * FF; idx += 256) {
        int c = idx >> 7, f = idx & 127;      // in is [c][f], reads coalesced
        sw[f * 66 + c] = __half_as_ushort(__float2half_rn(in[idx]));
    }
    __syncthreads();
    unsigned short* o = (unsigned short*)(g_kf16 + (size_t)blk * (FF * CC));
    for (int idx = threadIdx.x; idx < FF * CC; idx += 256) {
        int f = idx >> 6, c = idx & 63;
        o[idx] = sw[f * 66 + c];
    }
}

// ---------------------------------------------------------- main MMA kernel -
// Tile: M=128 (8 oh x 16 ow) x N=128 filters, K = 9 kp x 64 c. Single-pass
// fp16. A from once-converted fp16 halo; B in a 3-stage cp.async ring:
// per kp: wait_group 1 -> ONE sync -> issue B[kp+2] -> compute.
// Ring safety: stage (kp+2)%3 last held B[kp-1]; its consumers all passed
// this kp's sync. 8 warps: warp_m=wid&1, warp_n=wid>>1.
__global__ void __launch_bounds__(256, 2)
conv_mma_kernel(const float* __restrict__ x, float* __restrict__ out)
{
    extern __shared__ char smem[];
    const uint32_t sb = s2u(smem);
    const int tid  = threadIdx.x;
    const int lane = tid & 31;
    const int wid  = tid >> 5;
    const int warp_m = wid & 1;
    const int warp_n = wid >> 1;

    const int oh0 = (blockIdx.x >> 1) * 8;    // 4 oh-groups of 8 rows
    const int ow0 = (blockIdx.x & 1) * 16;    // 2 ow-groups of 16 cols
    const int img = blockIdx.y;
    const int b   = blockIdx.z;
    const float* xb = x + (size_t)(b * I_ + img) * (HH * WW * CC);
    const char* kf_base = (const char*)(g_kf16 + (size_t)(b * 9) * (FF * CC));

    // Prologue: pre-issue B[0] and B[1]; they land during halo convert.
    issue_b_stage(sb + BBASE + 0 * BSTAGE, kf_base, tid);
    issue_b_stage(sb + BBASE + 1 * BSTAGE, kf_base + (size_t)(FF * CC * 2), tid);

    // ---- Convert x halo once to fp16: rows r = ih_rel*18 + iw_rel ----------
    for (int idx = tid; idx < 180 * 16; idx += 256) {
        int r  = idx >> 4;            // halo row
        int c4 = idx & 15;            // float4 index within 64 c
        int ih = oh0 - 1 + r / 18;
        int iw = ow0 - 1 + r % 18;
        float4 v = make_float4(0.f, 0.f, 0.f, 0.f);
        if ((unsigned)ih < HH && (unsigned)iw < WW)
            v = *(const float4*)(xb + (ih * WW + iw) * CC + c4 * 4);
        __half2 h01 = __floats2half2_rn(v.x, v.y);
        __half2 h23 = __floats2half2_rn(v.z, v.w);
        uint32_t off = r * 128 + ((c4 * 8) ^ ((r & 7) << 4));   // swizzled
        *(uint2*)(smem + HALO + off) =
            make_uint2(*(uint32_t*)&h01, *(uint32_t*)&h23);
    }

    float acc[4][4][4];   // [mi][ni][reg]
    #pragma unroll
    for (int mi = 0; mi < 4; mi++)
        #pragma unroll
        for (int ni = 0; ni < 4; ni++)
            #pragma unroll
            for (int r = 0; r < 4; r++) acc[mi][ni][r] = 0.f;

    // per-lane ldmatrix address components
    const int a_m = lane & 15;                 // row within m16
    const int a_k = (lane >> 4) << 4;          // 0 / 16 byte (k half)
    const int b_n = (lane & 7) + ((lane >> 4) << 3);  // row within n16
    const int b_k = ((lane >> 3) & 1) << 4;    // 0 / 16 byte (k half)

    // halo row (minus rbase) for each mi:  m = oh_rel*16 + ow_rel
    int hrow[4];
    #pragma unroll
    for (int mi = 0; mi < 4; mi++) {
        int m = warp_m * 64 + mi * 16 + a_m;
        hrow[mi] = (m >> 4) * 18 + (m & 15);
    }
    // B ldsm row base + swizzle mask (XOR applied to FULL k-offset per ks)
    uint32_t brow[2], bmask[2];
    #pragma unroll
    for (int nj = 0; nj < 2; nj++) {
        int row = warp_n * 32 + nj * 16 + b_n;
        brow[nj]  = (uint32_t)row * 128;
        bmask[nj] = (uint32_t)((row & 7) << 4);
    }

    #pragma unroll 1
    for (int kp = 0; kp < 9; ++kp) {
        const int rbase = (kp / 3) * 18 + (kp % 3);
        const uint32_t Bcur = BBASE + (uint32_t)(kp % 3) * BSTAGE;

        // Retire B[kp]'s group (it is the oldest outstanding), then ONE sync.
        if (kp < 7) {
            asm volatile("cp.async.wait_group 1;" ::: "memory");
        } else {
            asm volatile("cp.async.wait_group 0;" ::: "memory");
        }
        __syncthreads();   // B[kp] visible to all; kp-1 compute fully drained
                           // (kp=0: also publishes the halo)

        // Refill the stage that held B[kp-1] (all its consumers passed the
        // sync above) with B[kp+2].
        if (kp < 7) {
            uint32_t Bnxt = BBASE + (uint32_t)((kp + 2) % 3) * BSTAGE;
            issue_b_stage(sb + Bnxt, kf_base + (size_t)(kp + 2) * (FF * CC * 2), tid);
        }

        // -- compute: 4 k16-steps, 16 MMAs each ------------------------------
        #pragma unroll
        for (int ks = 0; ks < 4; ++ks) {
            uint32_t ah[4][4];
            #pragma unroll
            for (int mi = 0; mi < 4; mi++) {
                int r = rbase + hrow[mi];
                uint32_t ro = (uint32_t)r * 128 + ((ks * 32 + a_k) ^ ((r & 7) << 4));
                ldsm4(ah[mi], sb + HALO + ro);
            }
            uint32_t bh[2][4];
            #pragma unroll
            for (int nj = 0; nj < 2; nj++)
                ldsm4(bh[nj], sb + Bcur + brow[nj] + ((ks * 32 + b_k) ^ bmask[nj]));
            #pragma unroll
            for (int mi = 0; mi < 4; mi++)
                #pragma unroll
                for (int ni = 0; ni < 4; ni++)
                    mma_f16(acc[mi][ni], ah[mi],
                            bh[ni >> 1][(ni & 1) * 2], bh[ni >> 1][(ni & 1) * 2 + 1]);
        }
        // No end-of-kp barrier: next iteration's top sync provides it.
    }

    // ---- epilogue: direct f32 stores (float2 per ni frag) ------------------
    const size_t obase = (size_t)(b * I_ + img) * (HH * WW);
    #pragma unroll
    for (int mi = 0; mi < 4; mi++) {
        #pragma unroll
        for (int half = 0; half < 2; half++) {
            int m  = warp_m * 64 + mi * 16 + (lane >> 2) + half * 8;
            int oh = oh0 + (m >> 4);
            int ow = ow0 + (m & 15);
            float* op = out + (obase + oh * WW + ow) * FF + warp_n * 32 + (lane & 3) * 2;
            #pragma unroll
            for (int ni = 0; ni < 4; ni++) {
                float2 v = make_float2(acc[mi][ni][half * 2], acc[mi][ni][half * 2 + 1]);
                *(float2*)(op + ni * 8) = v;
            }
        }
    }
}

// ----------------------------------------------------------------- launch ---
extern "C" void kernel_launch(void* const* d_in, const int* in_sizes, int n_in,
                              void* d_out, int out_size)
{
    const float* x = (const float*)d_in[0];   // (8,16,32,32,64) f32
    const float* k = (const float*)d_in[1];   // (8,3,3,64,128)  f32
    float* out = (float*)d_out;               // (8,16,32,32,128) f32

    cudaFuncSetAttribute(conv_mma_kernel,
                         cudaFuncAttributeMaxDynamicSharedMemorySize, SMEM_TOTAL);

    wt_convert_kernel<<<72, 256>>>(k);
    dim3 grid(8, 16, 8);                      // ((oh_grp, ow_grp), image, batch)
    conv_mma_kernel<<<grid, 256, SMEM_TOTAL>>>(x, out);
}